// round 1
// baseline (speedup 1.0000x reference)
#include <cuda_runtime.h>

#define HID 64
#define NBATCH 256
#define SEQ 4096
#define NG 256   // 4*HID gates

// Ping-pong hidden-sequence scratch (no cudaMalloc allowed): 2 x 256 MB.
__device__ float g_seqA[(size_t)NBATCH * SEQ * HID];
__device__ float g_seqB[(size_t)NBATCH * SEQ * HID];

static __device__ __forceinline__ unsigned long long pk2(float lo, float hi) {
    unsigned long long r;
    asm("mov.b64 %0, {%1,%2};" : "=l"(r) : "f"(lo), "f"(hi));
    return r;
}
static __device__ __forceinline__ void upk2(unsigned long long v, float& lo, float& hi) {
    asm("mov.b64 {%0,%1}, %2;" : "=f"(lo), "=f"(hi) : "l"(v));
}
// Packed fp32x2 FMA: d = a*b + d (per 32-bit lane). Only reachable via PTX.
static __device__ __forceinline__ void ffma2(unsigned long long& d,
                                             unsigned long long a,
                                             unsigned long long b) {
    asm("fma.rn.f32x2 %0, %1, %2, %0;" : "+l"(d) : "l"(a), "l"(b));
}

static __device__ __forceinline__ float sigmf(float x) {
    return 1.0f / (1.0f + __expf(-x));          // overflow-safe both directions
}
static __device__ __forceinline__ float tanh_f(float x) {
    return 1.0f - 2.0f / (__expf(2.0f * x) + 1.0f);  // exact limits at +/-inf
}

// ---------------------------------------------------------------------------
// Layer 0: DIN = 1.  Input x [B,S,1] -> g_seqA [B,S,64].
// Grid 128 CTAs x 256 threads; CTA owns batches (2*bx, 2*bx+1).
// Thread j computes gate j for both batches.  Whh row in 32 packed f32-pairs.
// ---------------------------------------------------------------------------
__global__ void __launch_bounds__(256, 1)
lstm_layer0_kernel(const float* __restrict__ x,
                   const float* __restrict__ Wih,   // [256,1]
                   const float* __restrict__ Whh,   // [256,64]
                   const float* __restrict__ bih,
                   const float* __restrict__ bhh,
                   float* __restrict__ d_out) {
    __shared__ __align__(16) float sh[2][HID];   // current h per batch
    __shared__ float sx[2];                      // current x scalar per batch
    __shared__ float sg[2][NG];                  // gates

    const int tid = threadIdx.x;
    const int j   = tid;
    const int b0  = blockIdx.x * 2;

    unsigned long long w[32];
#pragma unroll
    for (int p = 0; p < 32; ++p)
        w[p] = pk2(Whh[j * HID + 2 * p], Whh[j * HID + 2 * p + 1]);
    const float wx   = Wih[j];
    const float bias = bih[j] + bhh[j];

    if (tid < 128) sh[tid >> 6][tid & 63] = 0.0f;
    float c = 0.0f;

    // stagers: threads 128 (batch 0) and 192 (batch 1) pipeline the x scalars
    const int  sb   = (tid >> 6) & 1;
    const bool stgr = (tid >= 128) && ((tid & 63) == 0);
    const float* xp = x + (size_t)(b0 + sb) * SEQ;
    float x_cur = 0.0f, x_nxt = 0.0f;
    if (stgr) {
        sx[sb] = xp[0];
        x_cur  = xp[1];
        x_nxt  = xp[2];
    }
    __syncthreads();

    for (int t = 0; t < SEQ; ++t) {
        // ---- phase A: gate GEMV ----
        unsigned long long a0e = pk2(bias, 0.0f), a0o = pk2(0.0f, 0.0f);
        unsigned long long a1e = pk2(bias, 0.0f), a1o = pk2(0.0f, 0.0f);
        const ulonglong2* v0 = (const ulonglong2*)&sh[0][0];
        const ulonglong2* v1 = (const ulonglong2*)&sh[1][0];
#pragma unroll
        for (int p = 0; p < 16; ++p) {
            ulonglong2 q0 = v0[p];
            ffma2(a0e, w[2 * p], q0.x);
            ffma2(a0o, w[2 * p + 1], q0.y);
            ulonglong2 q1 = v1[p];
            ffma2(a1e, w[2 * p], q1.x);
            ffma2(a1o, w[2 * p + 1], q1.y);
        }
        float l0, h0, l1, h1;
        upk2(a0e, l0, h0); upk2(a0o, l1, h1);
        sg[0][j] = (l0 + h0) + (l1 + h1) + wx * sx[0];
        upk2(a1e, l0, h0); upk2(a1o, l1, h1);
        sg[1][j] = (l0 + h0) + (l1 + h1) + wx * sx[1];
        __syncthreads();

        // ---- phase B ----
        if (tid < 128) {
            const int ob = tid >> 6, ok = tid & 63;
            const float gi = sg[ob][ok];
            const float gf = sg[ob][HID + ok];
            const float gg = sg[ob][2 * HID + ok];
            const float go = sg[ob][3 * HID + ok];
            c = sigmf(gf) * c + sigmf(gi) * tanh_f(gg);
            const float h = sigmf(go) * tanh_f(c);
            sh[ob][ok] = h;
            g_seqA[(size_t)(b0 + ob) * SEQ * HID + (size_t)t * HID + ok] = h;
            if (t == SEQ - 1) {
                const size_t yoff = (size_t)NBATCH * SEQ;
                d_out[yoff + (size_t)(b0 + ob) * HID + ok] = h;                       // h_n[0]
                d_out[yoff + (size_t)3 * NBATCH * HID + (size_t)(b0 + ob) * HID + ok] = c; // c_n[0]
            }
        } else if (stgr) {
            if (t + 1 < SEQ) {
                sx[sb] = x_cur;
                x_cur  = x_nxt;
                if (t + 3 < SEQ) x_nxt = xp[t + 3];
            }
        }
        __syncthreads();
    }
}

// ---------------------------------------------------------------------------
// Layers 1/2: DIN = 64.  dir=0: g_seqA -> g_seqB ; dir=1: g_seqB -> g_seqA.
// Input vector per (batch,t) is [x_in(64) | h(64)] in smem; thread j holds the
// matching concatenated weight row [Wih_j | Whh_j] as 64 packed f32-pairs.
// ---------------------------------------------------------------------------
__global__ void __launch_bounds__(256, 1)
lstm_layer64_kernel(const float* __restrict__ Wih,   // [256,64]
                    const float* __restrict__ Whh,   // [256,64]
                    const float* __restrict__ bih,
                    const float* __restrict__ bhh,
                    float* __restrict__ d_out,
                    int layer, int dir) {
    const float* in_seq  = dir ? g_seqB : g_seqA;
    float*       out_seq = dir ? g_seqA : g_seqB;

    __shared__ __align__(16) float sv[2][2 * HID];  // [0..63]=x_in(t), [64..127]=h
    __shared__ float sg[2][NG];

    const int tid = threadIdx.x;
    const int j   = tid;
    const int b0  = blockIdx.x * 2;

    unsigned long long w[64];
#pragma unroll
    for (int p = 0; p < 32; ++p) {
        w[p]      = pk2(Wih[j * HID + 2 * p], Wih[j * HID + 2 * p + 1]);
        w[32 + p] = pk2(Whh[j * HID + 2 * p], Whh[j * HID + 2 * p + 1]);
    }
    const float bias = bih[j] + bhh[j];

    if (tid < 128) sv[tid >> 6][HID + (tid & 63)] = 0.0f;
    float c = 0.0f;

    // stagers (threads 128..255): pipeline input rows 3 steps ahead
    const int sb = (tid >> 6) & 1;
    const int sk = tid & 63;
    const float* ip = in_seq + (size_t)(b0 + sb) * SEQ * HID + sk;
    float x_cur = 0.0f, x_nxt = 0.0f;
    if (tid >= 128) {
        sv[sb][sk] = ip[0];
        x_cur = ip[HID];
        x_nxt = ip[2 * HID];
    }
    __syncthreads();

    for (int t = 0; t < SEQ; ++t) {
        // ---- phase A: gate GEMV over 128-length input vector ----
        unsigned long long a0e = pk2(bias, 0.0f), a0o = pk2(0.0f, 0.0f);
        unsigned long long a1e = pk2(bias, 0.0f), a1o = pk2(0.0f, 0.0f);
        const ulonglong2* v0 = (const ulonglong2*)&sv[0][0];
        const ulonglong2* v1 = (const ulonglong2*)&sv[1][0];
#pragma unroll
        for (int p = 0; p < 32; ++p) {
            ulonglong2 q0 = v0[p];
            ffma2(a0e, w[2 * p], q0.x);
            ffma2(a0o, w[2 * p + 1], q0.y);
            ulonglong2 q1 = v1[p];
            ffma2(a1e, w[2 * p], q1.x);
            ffma2(a1o, w[2 * p + 1], q1.y);
        }
        float l0, h0, l1, h1;
        upk2(a0e, l0, h0); upk2(a0o, l1, h1);
        sg[0][j] = (l0 + h0) + (l1 + h1);
        upk2(a1e, l0, h0); upk2(a1o, l1, h1);
        sg[1][j] = (l0 + h0) + (l1 + h1);
        __syncthreads();

        // ---- phase B ----
        if (tid < 128) {
            const int ob = tid >> 6, ok = tid & 63;
            const float gi = sg[ob][ok];
            const float gf = sg[ob][HID + ok];
            const float gg = sg[ob][2 * HID + ok];
            const float go = sg[ob][3 * HID + ok];
            c = sigmf(gf) * c + sigmf(gi) * tanh_f(gg);
            const float h = sigmf(go) * tanh_f(c);
            sv[ob][HID + ok] = h;
            out_seq[(size_t)(b0 + ob) * SEQ * HID + (size_t)t * HID + ok] = h;
            if (t == SEQ - 1) {
                const size_t yoff = (size_t)NBATCH * SEQ;
                d_out[yoff + (size_t)layer * NBATCH * HID + (size_t)(b0 + ob) * HID + ok] = h;
                d_out[yoff + (size_t)3 * NBATCH * HID + (size_t)layer * NBATCH * HID
                      + (size_t)(b0 + ob) * HID + ok] = c;
            }
        } else {
            if (t + 1 < SEQ) {
                sv[sb][sk] = x_cur;
                x_cur = x_nxt;
                if (t + 3 < SEQ) x_nxt = ip[(size_t)(t + 3) * HID];
            }
        }
        __syncthreads();
    }
}

// ---------------------------------------------------------------------------
// Final linear: y[r] = dot(g_seqA[r, :], Wlin) + blin, r = b*SEQ + t.
// One warp per row (grid-stride), coalesced 256B reads, shfl reduction.
// ---------------------------------------------------------------------------
__global__ void __launch_bounds__(256)
linear_kernel(const float* __restrict__ Wlin,
              const float* __restrict__ blin,
              float* __restrict__ y) {
    const int lane  = threadIdx.x & 31;
    const int warp  = (blockIdx.x * blockDim.x + threadIdx.x) >> 5;
    const int nwarp = (gridDim.x * blockDim.x) >> 5;
    const float w0 = Wlin[lane];
    const float w1 = Wlin[lane + 32];
    const float bl = blin[0];
    const int nrows = NBATCH * SEQ;
    for (int r = warp; r < nrows; r += nwarp) {
        const float* row = g_seqA + (size_t)r * HID;
        float s = row[lane] * w0 + row[lane + 32] * w1;
#pragma unroll
        for (int o = 16; o; o >>= 1) s += __shfl_down_sync(0xffffffffu, s, o);
        if (lane == 0) y[r] = s + bl;
    }
}

extern "C" void kernel_launch(void* const* d_in, const int* in_sizes, int n_in,
                              void* d_out, int out_size) {
    const float* x     = (const float*)d_in[0];
    const float* Wih0  = (const float*)d_in[1];
    const float* Whh0  = (const float*)d_in[2];
    const float* bih0  = (const float*)d_in[3];
    const float* bhh0  = (const float*)d_in[4];
    const float* Wih1  = (const float*)d_in[5];
    const float* Whh1  = (const float*)d_in[6];
    const float* bih1  = (const float*)d_in[7];
    const float* bhh1  = (const float*)d_in[8];
    const float* Wih2  = (const float*)d_in[9];
    const float* Whh2  = (const float*)d_in[10];
    const float* bih2  = (const float*)d_in[11];
    const float* bhh2  = (const float*)d_in[12];
    const float* Wlin  = (const float*)d_in[13];
    const float* blin  = (const float*)d_in[14];
    float* out = (float*)d_out;

    lstm_layer0_kernel<<<NBATCH / 2, 256>>>(x, Wih0, Whh0, bih0, bhh0, out);
    lstm_layer64_kernel<<<NBATCH / 2, 256>>>(Wih1, Whh1, bih1, bhh1, out, 1, 0);
    lstm_layer64_kernel<<<NBATCH / 2, 256>>>(Wih2, Whh2, bih2, bhh2, out, 2, 1);
    linear_kernel<<<1024, 256>>>(Wlin, blin, out);
}

// round 4
// speedup vs baseline: 1.0792x; 1.0792x over previous
#include <cuda_runtime.h>

#define HID 64
#define NBATCH 256
#define SEQ 4096
#define NG 256   // 4*HID gates

// Scratch (no cudaMalloc allowed):
__device__ float g_seqA[(size_t)NBATCH * SEQ * HID];   // 256 MB
__device__ float g_seqB[(size_t)NBATCH * SEQ * HID];   // 256 MB
__device__ float g_xz[(size_t)NBATCH * SEQ * NG];      // 1 GB: Wih@x + bias

typedef unsigned long long ull;

static __device__ __forceinline__ ull pk2(float lo, float hi) {
    ull r;
    asm("mov.b64 %0, {%1,%2};" : "=l"(r) : "f"(lo), "f"(hi));
    return r;
}
static __device__ __forceinline__ void upk2(ull v, float& lo, float& hi) {
    asm("mov.b64 {%0,%1}, %2;" : "=f"(lo), "=f"(hi) : "l"(v));
}
// Packed fp32x2 FMA: d = a*b + d (per 32-bit lane). Only reachable via PTX.
static __device__ __forceinline__ void ffma2(ull& d, ull a, ull b) {
    asm("fma.rn.f32x2 %0, %1, %2, %0;" : "+l"(d) : "l"(a), "l"(b));
}
static __device__ __forceinline__ float hsum4(ull a, ull b) {
    float x0, x1, y0, y1;
    upk2(a, x0, x1); upk2(b, y0, y1);
    return (x0 + x1) + (y0 + y1);
}

static __device__ __forceinline__ float sigmf(float x) {
    return 1.0f / (1.0f + __expf(-x));
}
static __device__ __forceinline__ float tanh_f(float x) {
    return 1.0f - 2.0f / (__expf(2.0f * x) + 1.0f);
}

// ---------------------------------------------------------------------------
// xz precompute, DIN = 1:  xz[b][t][j] = Wih[j] * x[b][t] + (bih[j]+bhh[j])
// grid (SEQ/64, NBATCH) x 256 threads.  Write-bound (1 GB).
// ---------------------------------------------------------------------------
__global__ void __launch_bounds__(256)
xz_din1_kernel(const float* __restrict__ x,
               const float* __restrict__ Wih,
               const float* __restrict__ bih,
               const float* __restrict__ bhh,
               float* __restrict__ xz) {
    __shared__ float sx[64];
    const int j  = threadIdx.x;
    const int b  = blockIdx.y;
    const int t0 = blockIdx.x * 64;
    if (j < 64) sx[j] = x[(size_t)b * SEQ + t0 + j];
    const float w    = Wih[j];
    const float bias = bih[j] + bhh[j];
    __syncthreads();
    float* o = xz + ((size_t)b * SEQ + t0) * NG + j;
#pragma unroll 8
    for (int tt = 0; tt < 64; ++tt)
        o[(size_t)tt * NG] = fmaf(w, sx[tt], bias);
}

// ---------------------------------------------------------------------------
// xz precompute, DIN = 64:  xz[b][t][j] = dot(Wih[j], in[b][t]) + bias[j]
// grid (SEQ/32, NBATCH) x 256 threads.  Thread j holds Wih row j (32 packed
// pairs) and produces 32 timesteps.  FFMA2-bound (~0.5 ms/layer).
// ---------------------------------------------------------------------------
__global__ void __launch_bounds__(256)
xz_din64_kernel(const float* __restrict__ in_seq,   // [B,SEQ,64]
                const float* __restrict__ Wih,      // [256,64]
                const float* __restrict__ bih,
                const float* __restrict__ bhh,
                float* __restrict__ xz) {
    __shared__ __align__(16) float sin_[32][HID];   // 8 KB
    const int j  = threadIdx.x;
    const int b  = blockIdx.y;
    const int t0 = blockIdx.x * 32;

    const float* src = in_seq + ((size_t)b * SEQ + t0) * HID;
#pragma unroll
    for (int k = 0; k < 8; ++k)
        ((float*)sin_)[j + k * 256] = src[j + k * 256];

    ull wi[32];
#pragma unroll
    for (int p = 0; p < 32; ++p)
        wi[p] = pk2(Wih[j * HID + 2 * p], Wih[j * HID + 2 * p + 1]);
    const float bias = bih[j] + bhh[j];
    __syncthreads();

    float* o = xz + ((size_t)b * SEQ + t0) * NG + j;
#pragma unroll 4
    for (int tt = 0; tt < 32; ++tt) {
        const ulonglong2* v = (const ulonglong2*)&sin_[tt][0];
        ull a0 = pk2(bias, 0.0f), a1 = 0ULL;
#pragma unroll
        for (int p = 0; p < 16; ++p) {
            ulonglong2 q = v[p];
            ffma2(a0, wi[2 * p], q.x);
            ffma2(a1, wi[2 * p + 1], q.y);
        }
        o[(size_t)tt * NG] = hsum4(a0, a1);
    }
}

// ---------------------------------------------------------------------------
// Recurrent kernel: 128 CTAs x 256 threads, CTA owns batches (2bx, 2bx+1).
// Thread j: Whh row j in 32 packed pairs (64 regs); per step computes the
// recurrent dot for gate j for both batches, adds the precomputed xz value
// (streamed from global via a 4-deep register ring), then threads 0..127 run
// the pointwise LSTM update.  Uniform control flow, 2 barriers per step.
// ---------------------------------------------------------------------------
__global__ void __launch_bounds__(256, 1)
lstm_rec_kernel(const float* __restrict__ xz,       // [B,SEQ,256] incl bias
                const float* __restrict__ Whh,      // [256,64]
                float* __restrict__ out_seq,        // [B,SEQ,64]
                float* __restrict__ d_out,
                int layer) {
    __shared__ __align__(16) float sh[2][HID];      // h(t-1)
    __shared__ float sgh[2][NG];                    // full gate pre-activation

    const int j  = threadIdx.x;
    const int b0 = blockIdx.x * 2;

    ull wh[32];
#pragma unroll
    for (int p = 0; p < 32; ++p)
        wh[p] = pk2(Whh[j * HID + 2 * p], Whh[j * HID + 2 * p + 1]);

    const float* z0 = xz + (size_t)b0 * SEQ * NG + j;
    const float* z1 = xz + (size_t)(b0 + 1) * SEQ * NG + j;
    float ring0[4], ring1[4];
#pragma unroll
    for (int d = 0; d < 4; ++d) {
        ring0[d] = z0[(size_t)d * NG];
        ring1[d] = z1[(size_t)d * NG];
    }

    const int pb = j >> 6, pu = j & 63;
    float c = 0.0f;
    if (j < 128) sh[pb][pu] = 0.0f;
    __syncthreads();

#pragma unroll 4
    for (int t = 0; t < SEQ; ++t) {
        // ---- recurrent GEMV over h(t-1), both batches ----
        const ulonglong2* v0 = (const ulonglong2*)&sh[0][0];
        const ulonglong2* v1 = (const ulonglong2*)&sh[1][0];
        ull a0 = 0ULL, a1 = 0ULL, a2 = 0ULL, a3 = 0ULL;
#pragma unroll
        for (int p = 0; p < 16; ++p) {
            ulonglong2 q0 = v0[p];
            ffma2(a0, wh[2 * p], q0.x);
            ffma2(a1, wh[2 * p + 1], q0.y);
            ulonglong2 q1 = v1[p];
            ffma2(a2, wh[2 * p], q1.x);
            ffma2(a3, wh[2 * p + 1], q1.y);
        }
        const int slot = t & 3;                 // static under unroll 4
        const float xz0v = ring0[slot];
        const float xz1v = ring1[slot];
        const int tp = (t + 4 < SEQ) ? (t + 4) : (SEQ - 1);
        ring0[slot] = z0[(size_t)tp * NG];      // prefetch 4 steps ahead
        ring1[slot] = z1[(size_t)tp * NG];
        sgh[0][j] = hsum4(a0, a1) + xz0v;
        sgh[1][j] = hsum4(a2, a3) + xz1v;
        __syncthreads();                        // gates visible

        // ---- pointwise update (threads 0..127) ----
        if (j < 128) {
            const float gi = sgh[pb][pu];
            const float gf = sgh[pb][HID + pu];
            const float gg = sgh[pb][2 * HID + pu];
            const float go = sgh[pb][3 * HID + pu];
            c = sigmf(gf) * c + sigmf(gi) * tanh_f(gg);
            const float h = sigmf(go) * tanh_f(c);
            sh[pb][pu] = h;
            out_seq[((size_t)(b0 + pb) * SEQ + t) * HID + pu] = h;
            if (t == SEQ - 1) {
                const size_t yoff = (size_t)NBATCH * SEQ;
                d_out[yoff + (size_t)layer * NBATCH * HID
                      + (size_t)(b0 + pb) * HID + pu] = h;
                d_out[yoff + (size_t)3 * NBATCH * HID + (size_t)layer * NBATCH * HID
                      + (size_t)(b0 + pb) * HID + pu] = c;
            }
        }
        __syncthreads();                        // h(t) visible
    }
}

// ---------------------------------------------------------------------------
// Final linear: y[r] = dot(g_seqA[r,:], Wlin) + blin.
// ---------------------------------------------------------------------------
__global__ void __launch_bounds__(256)
linear_kernel(const float* __restrict__ Wlin,
              const float* __restrict__ blin,
              float* __restrict__ y) {
    const int lane  = threadIdx.x & 31;
    const int warp  = (blockIdx.x * blockDim.x + threadIdx.x) >> 5;
    const int nwarp = (gridDim.x * blockDim.x) >> 5;
    const float w0 = Wlin[lane];
    const float w1 = Wlin[lane + 32];
    const float bl = blin[0];
    const int nrows = NBATCH * SEQ;
    for (int r = warp; r < nrows; r += nwarp) {
        const float* row = g_seqA + (size_t)r * HID;
        float s = row[lane] * w0 + row[lane + 32] * w1;
#pragma unroll
        for (int o = 16; o; o >>= 1) s += __shfl_down_sync(0xffffffffu, s, o);
        if (lane == 0) y[r] = s + bl;
    }
}

extern "C" void kernel_launch(void* const* d_in, const int* in_sizes, int n_in,
                              void* d_out, int out_size) {
    const float* x    = (const float*)d_in[0];
    const float* Wih0 = (const float*)d_in[1];
    const float* Whh0 = (const float*)d_in[2];
    const float* bih0 = (const float*)d_in[3];
    const float* bhh0 = (const float*)d_in[4];
    const float* Wih1 = (const float*)d_in[5];
    const float* Whh1 = (const float*)d_in[6];
    const float* bih1 = (const float*)d_in[7];
    const float* bhh1 = (const float*)d_in[8];
    const float* Wih2 = (const float*)d_in[9];
    const float* Whh2 = (const float*)d_in[10];
    const float* bih2 = (const float*)d_in[11];
    const float* bhh2 = (const float*)d_in[12];
    const float* Wlin = (const float*)d_in[13];
    const float* blin = (const float*)d_in[14];
    float* out = (float*)d_out;

    float* xzp;  cudaGetSymbolAddress((void**)&xzp, g_xz);
    float* sA;   cudaGetSymbolAddress((void**)&sA, g_seqA);
    float* sB;   cudaGetSymbolAddress((void**)&sB, g_seqB);

    xz_din1_kernel<<<dim3(SEQ / 64, NBATCH), 256>>>(x, Wih0, bih0, bhh0, xzp);
    lstm_rec_kernel<<<NBATCH / 2, 256>>>(xzp, Whh0, sA, out, 0);

    xz_din64_kernel<<<dim3(SEQ / 32, NBATCH), 256>>>(sA, Wih1, bih1, bhh1, xzp);
    lstm_rec_kernel<<<NBATCH / 2, 256>>>(xzp, Whh1, sB, out, 1);

    xz_din64_kernel<<<dim3(SEQ / 32, NBATCH), 256>>>(sB, Wih2, bih2, bhh2, xzp);
    lstm_rec_kernel<<<NBATCH / 2, 256>>>(xzp, Whh2, sA, out, 2);

    linear_kernel<<<1024, 256>>>(Wlin, blin, out);
}

// round 5
// speedup vs baseline: 1.1422x; 1.0584x over previous
#include <cuda_runtime.h>

#define HID 64
#define NBATCH 256
#define SEQ 4096
#define NG 256   // 4*HID gates

// Scratch (no cudaMalloc allowed):
__device__ float g_seqA[(size_t)NBATCH * SEQ * HID];   // 256 MB
__device__ float g_seqB[(size_t)NBATCH * SEQ * HID];   // 256 MB
__device__ float g_xz[(size_t)NBATCH * SEQ * NG];      // 1 GB: Wih@x + bias

typedef unsigned long long ull;

static __device__ __forceinline__ ull pk2(float lo, float hi) {
    ull r;
    asm("mov.b64 %0, {%1,%2};" : "=l"(r) : "f"(lo), "f"(hi));
    return r;
}
static __device__ __forceinline__ void upk2(ull v, float& lo, float& hi) {
    asm("mov.b64 {%0,%1}, %2;" : "=f"(lo), "=f"(hi) : "l"(v));
}
// Packed fp32x2 FMA: d = a*b + d (per 32-bit lane). Only reachable via PTX.
static __device__ __forceinline__ void ffma2(ull& d, ull a, ull b) {
    asm("fma.rn.f32x2 %0, %1, %2, %0;" : "+l"(d) : "l"(a), "l"(b));
}
static __device__ __forceinline__ float hsum4(ull a, ull b) {
    float x0, x1, y0, y1;
    upk2(a, x0, x1); upk2(b, y0, y1);
    return (x0 + x1) + (y0 + y1);
}

static __device__ __forceinline__ float sigmf(float x) {
    return 1.0f / (1.0f + __expf(-x));
}
static __device__ __forceinline__ float tanh_f(float x) {
    return 1.0f - 2.0f / (__expf(2.0f * x) + 1.0f);
}

// ---------------------------------------------------------------------------
// xz precompute, DIN = 1:  xz[b][t][j] = Wih[j] * x[b][t] + (bih[j]+bhh[j])
// ---------------------------------------------------------------------------
__global__ void __launch_bounds__(256)
xz_din1_kernel(const float* __restrict__ x,
               const float* __restrict__ Wih,
               const float* __restrict__ bih,
               const float* __restrict__ bhh,
               float* __restrict__ xz) {
    __shared__ float sx[64];
    const int j  = threadIdx.x;
    const int b  = blockIdx.y;
    const int t0 = blockIdx.x * 64;
    if (j < 64) sx[j] = x[(size_t)b * SEQ + t0 + j];
    const float w    = Wih[j];
    const float bias = bih[j] + bhh[j];
    __syncthreads();
    float* o = xz + ((size_t)b * SEQ + t0) * NG + j;
#pragma unroll 8
    for (int tt = 0; tt < 64; ++tt)
        o[(size_t)tt * NG] = fmaf(w, sx[tt], bias);
}

// ---------------------------------------------------------------------------
// xz precompute, DIN = 64:  xz[b][t][j] = dot(Wih[j], in[b][t]) + bias[j]
// ---------------------------------------------------------------------------
__global__ void __launch_bounds__(256)
xz_din64_kernel(const float* __restrict__ in_seq,   // [B,SEQ,64]
                const float* __restrict__ Wih,      // [256,64]
                const float* __restrict__ bih,
                const float* __restrict__ bhh,
                float* __restrict__ xz) {
    __shared__ __align__(16) float sin_[32][HID];   // 8 KB
    const int j  = threadIdx.x;
    const int b  = blockIdx.y;
    const int t0 = blockIdx.x * 32;

    const float* src = in_seq + ((size_t)b * SEQ + t0) * HID;
#pragma unroll
    for (int k = 0; k < 8; ++k)
        ((float*)sin_)[j + k * 256] = src[j + k * 256];

    ull wi[32];
#pragma unroll
    for (int p = 0; p < 32; ++p)
        wi[p] = pk2(Wih[j * HID + 2 * p], Wih[j * HID + 2 * p + 1]);
    const float bias = bih[j] + bhh[j];
    __syncthreads();

    float* o = xz + ((size_t)b * SEQ + t0) * NG + j;
#pragma unroll 4
    for (int tt = 0; tt < 32; ++tt) {
        const ulonglong2* v = (const ulonglong2*)&sin_[tt][0];
        ull a0 = pk2(bias, 0.0f), a1 = 0ULL;
#pragma unroll
        for (int p = 0; p < 16; ++p) {
            ulonglong2 q = v[p];
            ffma2(a0, wi[2 * p], q.x);
            ffma2(a1, wi[2 * p + 1], q.y);
        }
        o[(size_t)tt * NG] = hsum4(a0, a1);
    }
}

// ---------------------------------------------------------------------------
// Recurrent kernel v2: ONE batch per CTA, 256 CTAs x 256 threads,
// __launch_bounds__(256,2) so TWO independent CTAs co-reside per SM and hide
// each other's chain latency (R4 ncu: occ 12.5%, issue 20% -> latency-bound).
// Thread j holds Whh row j (32 packed pairs) and computes gate j each step;
// xz streamed via 4-deep register ring; threads 0..63 do the pointwise update.
// Same 2-barrier phase structure as the passing R4 kernel.
// ---------------------------------------------------------------------------
__global__ void __launch_bounds__(256, 2)
lstm_rec_kernel(const float* __restrict__ xz,       // [B,SEQ,256] incl bias
                const float* __restrict__ Whh,      // [256,64]
                float* __restrict__ out_seq,        // [B,SEQ,64]
                float* __restrict__ d_out,
                int layer) {
    __shared__ __align__(16) float sh[HID];         // h(t-1)
    __shared__ float sgh[NG];                       // gate pre-activations

    const int j = threadIdx.x;
    const int b = blockIdx.x;

    ull wh[32];
#pragma unroll
    for (int p = 0; p < 32; ++p)
        wh[p] = pk2(Whh[j * HID + 2 * p], Whh[j * HID + 2 * p + 1]);

    const float* z = xz + (size_t)b * SEQ * NG + j;
    float ring[4];
#pragma unroll
    for (int d = 0; d < 4; ++d)
        ring[d] = z[(size_t)d * NG];

    const int pu = j & 63;
    float c = 0.0f;
    if (j < 64) sh[pu] = 0.0f;
    __syncthreads();

#pragma unroll 4
    for (int t = 0; t < SEQ; ++t) {
        // ---- recurrent dot: sgh[j] = Whh[j] . h(t-1) + xz[b][t][j] ----
        const ulonglong2* v = (const ulonglong2*)&sh[0];
        ull a0 = 0ULL, a1 = 0ULL;
#pragma unroll
        for (int p = 0; p < 16; ++p) {
            ulonglong2 q = v[p];
            ffma2(a0, wh[2 * p], q.x);
            ffma2(a1, wh[2 * p + 1], q.y);
        }
        const int slot = t & 3;                 // static under unroll 4
        const float xzv = ring[slot];
        const int tp = (t + 4 < SEQ) ? (t + 4) : (SEQ - 1);
        ring[slot] = z[(size_t)tp * NG];        // prefetch 4 steps ahead
        sgh[j] = hsum4(a0, a1) + xzv;
        __syncthreads();                        // gates visible

        // ---- pointwise update (threads 0..63) ----
        if (j < 64) {
            const float gi = sgh[pu];
            const float gf = sgh[HID + pu];
            const float gg = sgh[2 * HID + pu];
            const float go = sgh[3 * HID + pu];
            c = sigmf(gf) * c + sigmf(gi) * tanh_f(gg);
            const float h = sigmf(go) * tanh_f(c);
            sh[pu] = h;
            out_seq[((size_t)b * SEQ + t) * HID + pu] = h;
            if (t == SEQ - 1) {
                const size_t yoff = (size_t)NBATCH * SEQ;
                d_out[yoff + (size_t)layer * NBATCH * HID
                      + (size_t)b * HID + pu] = h;
                d_out[yoff + (size_t)3 * NBATCH * HID + (size_t)layer * NBATCH * HID
                      + (size_t)b * HID + pu] = c;
            }
        }
        __syncthreads();                        // h(t) visible
    }
}

// ---------------------------------------------------------------------------
// Final linear: y[r] = dot(g_seqA[r,:], Wlin) + blin.
// ---------------------------------------------------------------------------
__global__ void __launch_bounds__(256)
linear_kernel(const float* __restrict__ Wlin,
              const float* __restrict__ blin,
              float* __restrict__ y) {
    const int lane  = threadIdx.x & 31;
    const int warp  = (blockIdx.x * blockDim.x + threadIdx.x) >> 5;
    const int nwarp = (gridDim.x * blockDim.x) >> 5;
    const float w0 = Wlin[lane];
    const float w1 = Wlin[lane + 32];
    const float bl = blin[0];
    const int nrows = NBATCH * SEQ;
    for (int r = warp; r < nrows; r += nwarp) {
        const float* row = g_seqA + (size_t)r * HID;
        float s = row[lane] * w0 + row[lane + 32] * w1;
#pragma unroll
        for (int o = 16; o; o >>= 1) s += __shfl_down_sync(0xffffffffu, s, o);
        if (lane == 0) y[r] = s + bl;
    }
}

extern "C" void kernel_launch(void* const* d_in, const int* in_sizes, int n_in,
                              void* d_out, int out_size) {
    const float* x    = (const float*)d_in[0];
    const float* Wih0 = (const float*)d_in[1];
    const float* Whh0 = (const float*)d_in[2];
    const float* bih0 = (const float*)d_in[3];
    const float* bhh0 = (const float*)d_in[4];
    const float* Wih1 = (const float*)d_in[5];
    const float* Whh1 = (const float*)d_in[6];
    const float* bih1 = (const float*)d_in[7];
    const float* bhh1 = (const float*)d_in[8];
    const float* Wih2 = (const float*)d_in[9];
    const float* Whh2 = (const float*)d_in[10];
    const float* bih2 = (const float*)d_in[11];
    const float* bhh2 = (const float*)d_in[12];
    const float* Wlin = (const float*)d_in[13];
    const float* blin = (const float*)d_in[14];
    float* out = (float*)d_out;

    float* xzp;  cudaGetSymbolAddress((void**)&xzp, g_xz);
    float* sA;   cudaGetSymbolAddress((void**)&sA, g_seqA);
    float* sB;   cudaGetSymbolAddress((void**)&sB, g_seqB);

    xz_din1_kernel<<<dim3(SEQ / 64, NBATCH), 256>>>(x, Wih0, bih0, bhh0, xzp);
    lstm_rec_kernel<<<NBATCH, 256>>>(xzp, Whh0, sA, out, 0);

    xz_din64_kernel<<<dim3(SEQ / 32, NBATCH), 256>>>(sA, Wih1, bih1, bhh1, xzp);
    lstm_rec_kernel<<<NBATCH, 256>>>(xzp, Whh1, sB, out, 1);

    xz_din64_kernel<<<dim3(SEQ / 32, NBATCH), 256>>>(sB, Wih2, bih2, bhh2, xzp);
    lstm_rec_kernel<<<NBATCH, 256>>>(xzp, Whh2, sA, out, 2);

    linear_kernel<<<1024, 256>>>(Wlin, blin, out);
}

// round 6
// speedup vs baseline: 1.3120x; 1.1486x over previous
#include <cuda_runtime.h>

#define HID 64
#define NBATCH 256
#define SEQ 4096
#define NG 256   // 4*HID gates

// Scratch (no cudaMalloc allowed):
__device__ float g_seqA[(size_t)NBATCH * SEQ * HID];   // 256 MB
__device__ float g_seqB[(size_t)NBATCH * SEQ * HID];   // 256 MB
__device__ float g_xz[(size_t)NBATCH * SEQ * NG];      // 1 GB: Wih@x + bias

typedef unsigned long long ull;

static __device__ __forceinline__ ull pk2(float lo, float hi) {
    ull r;
    asm("mov.b64 %0, {%1,%2};" : "=l"(r) : "f"(lo), "f"(hi));
    return r;
}
static __device__ __forceinline__ void upk2(ull v, float& lo, float& hi) {
    asm("mov.b64 {%0,%1}, %2;" : "=f"(lo), "=f"(hi) : "l"(v));
}
// Packed fp32x2 FMA: d = a*b + d (per 32-bit lane). Only reachable via PTX.
static __device__ __forceinline__ void ffma2(ull& d, ull a, ull b) {
    asm("fma.rn.f32x2 %0, %1, %2, %0;" : "+l"(d) : "l"(a), "l"(b));
}
static __device__ __forceinline__ float hsum8(ull a, ull b, ull c, ull d) {
    float x0, x1, y0, y1, z0, z1, w0, w1;
    upk2(a, x0, x1); upk2(b, y0, y1); upk2(c, z0, z1); upk2(d, w0, w1);
    return ((x0 + x1) + (y0 + y1)) + ((z0 + z1) + (w0 + w1));
}

static __device__ __forceinline__ float sigmf(float x) {
    return 1.0f / (1.0f + __expf(-x));
}
static __device__ __forceinline__ float tanh_f(float x) {
    return 1.0f - 2.0f / (__expf(2.0f * x) + 1.0f);
}

// ---------------------------------------------------------------------------
// xz precompute, DIN = 1:  xz[b][t][j] = Wih[j] * x[b][t] + (bih[j]+bhh[j])
// ---------------------------------------------------------------------------
__global__ void __launch_bounds__(256)
xz_din1_kernel(const float* __restrict__ x,
               const float* __restrict__ Wih,
               const float* __restrict__ bih,
               const float* __restrict__ bhh,
               float* __restrict__ xz) {
    __shared__ float sx[64];
    const int j  = threadIdx.x;
    const int b  = blockIdx.y;
    const int t0 = blockIdx.x * 64;
    if (j < 64) sx[j] = x[(size_t)b * SEQ + t0 + j];
    const float w    = Wih[j];
    const float bias = bih[j] + bhh[j];
    __syncthreads();
    float* o = xz + ((size_t)b * SEQ + t0) * NG + j;
#pragma unroll 8
    for (int tt = 0; tt < 64; ++tt)
        o[(size_t)tt * NG] = fmaf(w, sx[tt], bias);
}

// ---------------------------------------------------------------------------
// xz precompute, DIN = 64:  xz[b][t][j] = dot(Wih[j], in[b][t]) + bias[j]
// ---------------------------------------------------------------------------
__global__ void __launch_bounds__(256)
xz_din64_kernel(const float* __restrict__ in_seq,   // [B,SEQ,64]
                const float* __restrict__ Wih,      // [256,64]
                const float* __restrict__ bih,
                const float* __restrict__ bhh,
                float* __restrict__ xz) {
    __shared__ __align__(16) float sin_[32][HID];   // 8 KB
    const int j  = threadIdx.x;
    const int b  = blockIdx.y;
    const int t0 = blockIdx.x * 32;

    const float* src = in_seq + ((size_t)b * SEQ + t0) * HID;
#pragma unroll
    for (int k = 0; k < 8; ++k)
        ((float*)sin_)[j + k * 256] = src[j + k * 256];

    ull wi[32];
#pragma unroll
    for (int p = 0; p < 32; ++p)
        wi[p] = pk2(Wih[j * HID + 2 * p], Wih[j * HID + 2 * p + 1]);
    const float bias = bih[j] + bhh[j];
    __syncthreads();

    float* o = xz + ((size_t)b * SEQ + t0) * NG + j;
#pragma unroll 4
    for (int tt = 0; tt < 32; ++tt) {
        const ulonglong2* v = (const ulonglong2*)&sin_[tt][0];
        ull a0 = pk2(bias, 0.0f), a1 = 0ULL;
#pragma unroll
        for (int p = 0; p < 16; ++p) {
            ulonglong2 q = v[p];
            ffma2(a0, wi[2 * p], q.x);
            ffma2(a1, wi[2 * p + 1], q.y);
        }
        float l0, l1, h0, h1;
        upk2(a0, l0, h0); upk2(a1, l1, h1);
        o[(size_t)tt * NG] = (l0 + h0) + (l1 + h1);
    }
}

// ---------------------------------------------------------------------------
// Recurrent kernel v3: ONE batch per CTA, 256 CTAs x 256 threads, 2 CTAs/SM.
// Gate remap: tid = 4*u + type (type: 0=i,1=f,2=g,3=o), so all 4 gates of a
// unit sit in adjacent lanes of one warp.  Pointwise update is done with 4
// intra-warp shuffles + redundant per-lane math -> NO smem round trip, runs
// on all 8 warps.  ONE __syncthreads per step (h double-buffered).
// ---------------------------------------------------------------------------
__global__ void __launch_bounds__(256, 2)
lstm_rec_kernel(const float* __restrict__ xz,       // [B,SEQ,256] incl bias
                const float* __restrict__ Whh,      // [256,64]
                float* __restrict__ out_seq,        // [B,SEQ,64]
                float* __restrict__ d_out,
                int layer) {
    __shared__ __align__(16) float sh[2][HID];      // double-buffered h

    const int tid  = threadIdx.x;
    const int b    = blockIdx.x;
    const int u    = tid >> 2;          // hidden unit 0..63
    const int type = tid & 3;           // 0=i,1=f,2=g,3=o
    const int j    = type * HID + u;    // gate row in PyTorch order
    const int lane = tid & 31;
    const int lbase = lane & ~3;        // first lane of this unit's quad

    ull wh[32];
#pragma unroll
    for (int p = 0; p < 32; ++p)
        wh[p] = pk2(Whh[j * HID + 2 * p], Whh[j * HID + 2 * p + 1]);

    const float* z = xz + (size_t)b * SEQ * NG + j;
    float ring[4];
#pragma unroll
    for (int d = 0; d < 4; ++d)
        ring[d] = z[(size_t)d * NG];

    float c = 0.0f;
    if (tid < 128) sh[tid >> 6][tid & 63] = 0.0f;
    __syncthreads();

#pragma unroll 4
    for (int t = 0; t < SEQ; ++t) {
        const int par = t & 1;                      // static under unroll
        // ---- recurrent dot: g = Whh[j] . h(t-1) + xz[b][t][j] ----
        const ulonglong2* v = (const ulonglong2*)&sh[par][0];
        ull a0 = 0ULL, a1 = 0ULL, a2 = 0ULL, a3 = 0ULL;
#pragma unroll
        for (int p = 0; p < 8; ++p) {
            ulonglong2 qa = v[2 * p];
            ffma2(a0, wh[4 * p], qa.x);
            ffma2(a1, wh[4 * p + 1], qa.y);
            ulonglong2 qb = v[2 * p + 1];
            ffma2(a2, wh[4 * p + 2], qb.x);
            ffma2(a3, wh[4 * p + 3], qb.y);
        }
        const int slot = t & 3;                     // static under unroll
        const float g = hsum8(a0, a1, a2, a3) + ring[slot];
        const int tp = (t + 4 < SEQ) ? (t + 4) : (SEQ - 1);
        ring[slot] = z[(size_t)tp * NG];            // prefetch 4 ahead

        // ---- gather the unit's 4 gates via intra-warp shuffle ----
        const float gi = __shfl_sync(0xffffffffu, g, lbase + 0, 32);
        const float gf = __shfl_sync(0xffffffffu, g, lbase + 1, 32);
        const float gg = __shfl_sync(0xffffffffu, g, lbase + 2, 32);
        const float go = __shfl_sync(0xffffffffu, g, lbase + 3, 32);

        // ---- pointwise update (all lanes, redundant per quad) ----
        c = sigmf(gf) * c + sigmf(gi) * tanh_f(gg);
        const float h = sigmf(go) * tanh_f(c);
        if (type == 0) {
            sh[par ^ 1][u] = h;
            out_seq[((size_t)b * SEQ + t) * HID + u] = h;
            if (t == SEQ - 1) {
                const size_t yoff = (size_t)NBATCH * SEQ;
                d_out[yoff + (size_t)layer * NBATCH * HID + (size_t)b * HID + u] = h;
                d_out[yoff + (size_t)3 * NBATCH * HID + (size_t)layer * NBATCH * HID
                      + (size_t)b * HID + u] = c;
            }
        }
        __syncthreads();                            // h(t) visible
    }
}

// ---------------------------------------------------------------------------
// Final linear: y[r] = dot(g_seqA[r,:], Wlin) + blin.
// ---------------------------------------------------------------------------
__global__ void __launch_bounds__(256)
linear_kernel(const float* __restrict__ Wlin,
              const float* __restrict__ blin,
              float* __restrict__ y) {
    const int lane  = threadIdx.x & 31;
    const int warp  = (blockIdx.x * blockDim.x + threadIdx.x) >> 5;
    const int nwarp = (gridDim.x * blockDim.x) >> 5;
    const float w0 = Wlin[lane];
    const float w1 = Wlin[lane + 32];
    const float bl = blin[0];
    const int nrows = NBATCH * SEQ;
    for (int r = warp; r < nrows; r += nwarp) {
        const float* row = g_seqA + (size_t)r * HID;
        float s = row[lane] * w0 + row[lane + 32] * w1;
#pragma unroll
        for (int o = 16; o; o >>= 1) s += __shfl_down_sync(0xffffffffu, s, o);
        if (lane == 0) y[r] = s + bl;
    }
}

extern "C" void kernel_launch(void* const* d_in, const int* in_sizes, int n_in,
                              void* d_out, int out_size) {
    const float* x    = (const float*)d_in[0];
    const float* Wih0 = (const float*)d_in[1];
    const float* Whh0 = (const float*)d_in[2];
    const float* bih0 = (const float*)d_in[3];
    const float* bhh0 = (const float*)d_in[4];
    const float* Wih1 = (const float*)d_in[5];
    const float* Whh1 = (const float*)d_in[6];
    const float* bih1 = (const float*)d_in[7];
    const float* bhh1 = (const float*)d_in[8];
    const float* Wih2 = (const float*)d_in[9];
    const float* Whh2 = (const float*)d_in[10];
    const float* bih2 = (const float*)d_in[11];
    const float* bhh2 = (const float*)d_in[12];
    const float* Wlin = (const float*)d_in[13];
    const float* blin = (const float*)d_in[14];
    float* out = (float*)d_out;

    float* xzp;  cudaGetSymbolAddress((void**)&xzp, g_xz);
    float* sA;   cudaGetSymbolAddress((void**)&sA, g_seqA);
    float* sB;   cudaGetSymbolAddress((void**)&sB, g_seqB);

    xz_din1_kernel<<<dim3(SEQ / 64, NBATCH), 256>>>(x, Wih0, bih0, bhh0, xzp);
    lstm_rec_kernel<<<NBATCH, 256>>>(xzp, Whh0, sA, out, 0);

    xz_din64_kernel<<<dim3(SEQ / 32, NBATCH), 256>>>(sA, Wih1, bih1, bhh1, xzp);
    lstm_rec_kernel<<<NBATCH, 256>>>(xzp, Whh1, sB, out, 1);

    xz_din64_kernel<<<dim3(SEQ / 32, NBATCH), 256>>>(sB, Wih2, bih2, bhh2, xzp);
    lstm_rec_kernel<<<NBATCH, 256>>>(xzp, Whh2, sA, out, 2);

    linear_kernel<<<1024, 256>>>(Wlin, blin, out);
}

// round 7
// speedup vs baseline: 1.6300x; 1.2424x over previous
#include <cuda_runtime.h>

#define HID 64
#define NBATCH 256
#define SEQ 4096
#define NG 256   // 4*HID gates

// Scratch (no cudaMalloc allowed):
__device__ float g_seqA[(size_t)NBATCH * SEQ * HID];   // 256 MB
__device__ float g_seqB[(size_t)NBATCH * SEQ * HID];   // 256 MB
__device__ float g_xz[(size_t)NBATCH * SEQ * NG];      // 1 GB, gate-remapped

typedef unsigned long long ull;

static __device__ __forceinline__ ull pk2(float lo, float hi) {
    ull r;
    asm("mov.b64 %0, {%1,%2};" : "=l"(r) : "f"(lo), "f"(hi));
    return r;
}
static __device__ __forceinline__ void upk2(ull v, float& lo, float& hi) {
    asm("mov.b64 {%0,%1}, %2;" : "=f"(lo), "=f"(hi) : "l"(v));
}
static __device__ __forceinline__ void ffma2(ull& d, ull a, ull b) {
    asm("fma.rn.f32x2 %0, %1, %2, %0;" : "+l"(d) : "l"(a), "l"(b));
}
static __device__ __forceinline__ float ex2f(float x) {
    float r; asm("ex2.approx.f32 %0, %1;" : "=f"(r) : "f"(x)); return r;
}
static __device__ __forceinline__ float rcpf(float x) {
    float r; asm("rcp.approx.f32 %0, %1;" : "=f"(r) : "f"(x)); return r;
}
#define L2E 1.44269504088896f
// tanh(x) = 1 - 2/(2^(2*L2E*x)+1); overflow-safe both directions.
static __device__ __forceinline__ float tanh_f(float x) {
    return fmaf(-2.0f, rcpf(ex2f(x * (2.0f * L2E)) + 1.0f), 1.0f);
}

// gate remap: storage index tid <-> gate row jg = (tid&3)*HID + (tid>>2)
// (type q = tid&3 in PyTorch order i,f,g,o; unit u = tid>>2)

// ---------------------------------------------------------------------------
// xz precompute, DIN = 1 (gate-remapped output)
// ---------------------------------------------------------------------------
__global__ void __launch_bounds__(256)
xz_din1_kernel(const float* __restrict__ x,
               const float* __restrict__ Wih,
               const float* __restrict__ bih,
               const float* __restrict__ bhh,
               float* __restrict__ xz) {
    __shared__ float sx[64];
    const int tid = threadIdx.x;
    const int jg  = (tid & 3) * HID + (tid >> 2);
    const int b   = blockIdx.y;
    const int t0  = blockIdx.x * 64;
    if (tid < 64) sx[tid] = x[(size_t)b * SEQ + t0 + tid];
    const float w    = Wih[jg];
    const float bias = bih[jg] + bhh[jg];
    __syncthreads();
    float* o = xz + ((size_t)b * SEQ + t0) * NG + tid;
#pragma unroll 8
    for (int tt = 0; tt < 64; ++tt)
        o[(size_t)tt * NG] = fmaf(w, sx[tt], bias);
}

// ---------------------------------------------------------------------------
// xz precompute, DIN = 64 (gate-remapped output)
// ---------------------------------------------------------------------------
__global__ void __launch_bounds__(256)
xz_din64_kernel(const float* __restrict__ in_seq,   // [B,SEQ,64]
                const float* __restrict__ Wih,      // [256,64]
                const float* __restrict__ bih,
                const float* __restrict__ bhh,
                float* __restrict__ xz) {
    __shared__ __align__(16) float sin_[32][HID];   // 8 KB
    const int tid = threadIdx.x;
    const int jg  = (tid & 3) * HID + (tid >> 2);
    const int b   = blockIdx.y;
    const int t0  = blockIdx.x * 32;

    const float* src = in_seq + ((size_t)b * SEQ + t0) * HID;
#pragma unroll
    for (int k = 0; k < 8; ++k)
        ((float*)sin_)[tid + k * 256] = src[tid + k * 256];

    ull wi[32];
#pragma unroll
    for (int p = 0; p < 32; ++p)
        wi[p] = pk2(Wih[jg * HID + 2 * p], Wih[jg * HID + 2 * p + 1]);
    const float bias = bih[jg] + bhh[jg];
    __syncthreads();

    float* o = xz + ((size_t)b * SEQ + t0) * NG + tid;
#pragma unroll 4
    for (int tt = 0; tt < 32; ++tt) {
        const ulonglong2* v = (const ulonglong2*)&sin_[tt][0];
        ull a0 = pk2(bias, 0.0f), a1 = 0ULL;
#pragma unroll
        for (int p = 0; p < 16; ++p) {
            ulonglong2 q = v[p];
            ffma2(a0, wi[2 * p], q.x);
            ffma2(a1, wi[2 * p + 1], q.y);
        }
        float l0, l1, h0, h1;
        upk2(a0, l0, h0); upk2(a1, l1, h1);
        o[(size_t)tt * NG] = (l0 + h0) + (l1 + h1);
    }
}

// ---------------------------------------------------------------------------
// Recurrent kernel v4.  1 batch/CTA, 256 CTAs x 256 threads, 2 CTAs/SM.
// Thread (u = tid>>2, q = tid&3): computes PARTIAL dots of ALL 4 gates of
// unit u over h-chunk q (16 elems -> 4 LDS.128), quad reduce-scatter via
// 3 shuffles leaves lane q holding gate-q preactivation.  Unified
// branch-free activation (1 ex2 + 1 rcp), no redundancy.  1 barrier/step.
// h double-buffered in padded smem (stride 20 -> conflict-free LDS.128).
// ---------------------------------------------------------------------------
__global__ void __launch_bounds__(256, 2)
lstm_rec_kernel(const float* __restrict__ xz,       // [B,SEQ,256] remapped
                const float* __restrict__ Whh,      // [256,64]
                float* __restrict__ out_seq,        // [B,SEQ,64]
                float* __restrict__ d_out,
                int layer) {
    __shared__ __align__(16) float sh[2][80];       // 4 chunks * stride 20

    const int tid = threadIdx.x;
    const int b   = blockIdx.x;
    const int u   = tid >> 2;
    const int q   = tid & 3;

    // weights: 4 gate rows of unit u, columns [16q, 16q+16)
    ull w[32];
#pragma unroll
    for (int g = 0; g < 4; ++g) {
        const int row = g * HID + u;
#pragma unroll
        for (int m = 0; m < 8; ++m)
            w[g * 8 + m] = pk2(Whh[row * HID + 16 * q + 2 * m],
                               Whh[row * HID + 16 * q + 2 * m + 1]);
    }

    const float* z = xz + (size_t)b * SEQ * NG + tid;
    float ring[4];
#pragma unroll
    for (int d = 0; d < 4; ++d)
        ring[d] = z[(size_t)d * NG];

    // activation constants: lane's own gate is tanh iff q==2
    const float sA  = (q == 2) ? 2.0f : 1.0f;       // subtract coeff
    const float kA  = sA * L2E;                     // ex2 scale

    float c = 0.0f, hlast = 0.0f;
    if (tid < 128) sh[tid / 80 == 0 ? 0 : 1][tid % 80] = 0.0f;  // zero both bufs' 80 floats? (see below)
    // simpler & safe: zero both buffers fully
    if (tid < 160) sh[tid / 80][tid % 80] = 0.0f;
    __syncthreads();

#pragma unroll 4
    for (int t = 0; t < SEQ; ++t) {
        const int par  = t & 1;                     // static under unroll
        const int slot = t & 3;

        // ---- partial dots: 4 gates over h-chunk q ----
        const ulonglong2* v = (const ulonglong2*)&sh[par][20 * q];
        ull ac0 = 0ULL, ac1 = 0ULL, ac2 = 0ULL, ac3 = 0ULL;
#pragma unroll
        for (int p = 0; p < 4; ++p) {
            ulonglong2 d = v[p];
            ffma2(ac0, w[0 * 8 + 2 * p], d.x); ffma2(ac0, w[0 * 8 + 2 * p + 1], d.y);
            ffma2(ac1, w[1 * 8 + 2 * p], d.x); ffma2(ac1, w[1 * 8 + 2 * p + 1], d.y);
            ffma2(ac2, w[2 * 8 + 2 * p], d.x); ffma2(ac2, w[2 * 8 + 2 * p + 1], d.y);
            ffma2(ac3, w[3 * 8 + 2 * p], d.x); ffma2(ac3, w[3 * 8 + 2 * p + 1], d.y);
        }
        float pi, pf, pg, po, lo, hi;
        upk2(ac0, lo, hi); pi = lo + hi;
        upk2(ac1, lo, hi); pf = lo + hi;
        upk2(ac2, lo, hi); pg = lo + hi;
        upk2(ac3, lo, hi); po = lo + hi;

        // ---- quad reduce-scatter: lane q ends with gate-q total ----
        // round 1 (xor 2): lanes 0,1 keep (i,f); lanes 2,3 keep (g,o)
        const bool lowq = (q < 2);
        float sX = lowq ? pg : pi;
        float sY = lowq ? po : pf;
        float kX = lowq ? pi : pg;
        float kY = lowq ? pf : po;
        kX += __shfl_xor_sync(0xffffffffu, sX, 2, 32);
        kY += __shfl_xor_sync(0xffffffffu, sY, 2, 32);
        // round 2 (xor 1): even lane keeps X, odd keeps Y
        const bool oddq = (q & 1);
        float snd = oddq ? kX : kY;
        float tot = (oddq ? kY : kX) + __shfl_xor_sync(0xffffffffu, snd, 1, 32);

        const float g = tot + ring[slot];
        const int tp = (t + 4 < SEQ) ? (t + 4) : (SEQ - 1);
        ring[slot] = z[(size_t)tp * NG];            // prefetch 4 ahead

        // ---- own-gate activation (branch-free, 1 ex2 + 1 rcp) ----
        const float a = fmaf(-sA, rcpf(ex2f(g * kA) + 1.0f), 1.0f);

        // ---- gather quad activations, pointwise update ----
        const float ai = __shfl_sync(0xffffffffu, a, (tid & 31) & ~3, 32);
        const float af = __shfl_sync(0xffffffffu, a, ((tid & 31) & ~3) + 1, 32);
        const float ag = __shfl_sync(0xffffffffu, a, ((tid & 31) & ~3) + 2, 32);
        const float ao = __shfl_sync(0xffffffffu, a, ((tid & 31) & ~3) + 3, 32);
        c = fmaf(af, c, ai * ag);
        const float h = ao * tanh_f(c);
        hlast = h;
        if (q == 0) {
            sh[par ^ 1][20 * (u >> 4) + (u & 15)] = h;
            out_seq[((size_t)b * SEQ + t) * HID + u] = h;
        }
        __syncthreads();                            // h(t) visible
    }

    if (q == 0) {
        const size_t yoff = (size_t)NBATCH * SEQ;
        d_out[yoff + (size_t)layer * NBATCH * HID + (size_t)b * HID + u] = hlast;
        d_out[yoff + (size_t)3 * NBATCH * HID + (size_t)layer * NBATCH * HID
              + (size_t)b * HID + u] = c;
    }
}

// ---------------------------------------------------------------------------
// Final linear: y[r] = dot(g_seqA[r,:], Wlin) + blin.
// ---------------------------------------------------------------------------
__global__ void __launch_bounds__(256)
linear_kernel(const float* __restrict__ Wlin,
              const float* __restrict__ blin,
              float* __restrict__ y) {
    const int lane  = threadIdx.x & 31;
    const int warp  = (blockIdx.x * blockDim.x + threadIdx.x) >> 5;
    const int nwarp = (gridDim.x * blockDim.x) >> 5;
    const float w0 = Wlin[lane];
    const float w1 = Wlin[lane + 32];
    const float bl = blin[0];
    const int nrows = NBATCH * SEQ;
    for (int r = warp; r < nrows; r += nwarp) {
        const float* row = g_seqA + (size_t)r * HID;
        float s = row[lane] * w0 + row[lane + 32] * w1;
#pragma unroll
        for (int o = 16; o; o >>= 1) s += __shfl_down_sync(0xffffffffu, s, o);
        if (lane == 0) y[r] = s + bl;
    }
}

extern "C" void kernel_launch(void* const* d_in, const int* in_sizes, int n_in,
                              void* d_out, int out_size) {
    const float* x    = (const float*)d_in[0];
    const float* Wih0 = (const float*)d_in[1];
    const float* Whh0 = (const float*)d_in[2];
    const float* bih0 = (const float*)d_in[3];
    const float* bhh0 = (const float*)d_in[4];
    const float* Wih1 = (const float*)d_in[5];
    const float* Whh1 = (const float*)d_in[6];
    const float* bih1 = (const float*)d_in[7];
    const float* bhh1 = (const float*)d_in[8];
    const float* Wih2 = (const float*)d_in[9];
    const float* Whh2 = (const float*)d_in[10];
    const float* bih2 = (const float*)d_in[11];
    const float* bhh2 = (const float*)d_in[12];
    const float* Wlin = (const float*)d_in[13];
    const float* blin = (const float*)d_in[14];
    float* out = (float*)d_out;

    float* xzp;  cudaGetSymbolAddress((void**)&xzp, g_xz);
    float* sA;   cudaGetSymbolAddress((void**)&sA, g_seqA);
    float* sB;   cudaGetSymbolAddress((void**)&sB, g_seqB);

    xz_din1_kernel<<<dim3(SEQ / 64, NBATCH), 256>>>(x, Wih0, bih0, bhh0, xzp);
    lstm_rec_kernel<<<NBATCH, 256>>>(xzp, Whh0, sA, out, 0);

    xz_din64_kernel<<<dim3(SEQ / 32, NBATCH), 256>>>(sA, Wih1, bih1, bhh1, xzp);
    lstm_rec_kernel<<<NBATCH, 256>>>(xzp, Whh1, sB, out, 1);

    xz_din64_kernel<<<dim3(SEQ / 32, NBATCH), 256>>>(sB, Wih2, bih2, bhh2, xzp);
    lstm_rec_kernel<<<NBATCH, 256>>>(xzp, Whh2, sA, out, 2);

    linear_kernel<<<1024, 256>>>(Wlin, blin, out);
}